// round 14
// baseline (speedup 1.0000x reference)
#include <cuda_runtime.h>
#include <cstdint>
#include <cstddef>

// Problem constants
#define T_STEPS 512
#define BATCH   128
#define N_INP   256
#define N_HID   1024
#define N_OUT   128

// Two-group persistent config
#define SPLITK  8                  // k-split (K=1024 -> 128/slice)
#define KSLICE  128
#define KP      (KSLICE / 2)       // 64 float2 k-pairs
#define BT      64                 // batch rows per group
#define TPC     128                // threads per CTA
#define GCTA    128                // CTAs per group (grid = 256, 2 per SM)
#define LDP     65                 // padded row pitch (float2): 520B rows

// xproj tiling (R7-exact)
#define KC      32
#define KPAIRS  (KC / 2)

// -------- scratch (device globals; no runtime allocation allowed) --------
__device__ float g_xp[(size_t)T_STEPS * BATCH * N_HID];     // input projection (+biases)
__device__ float g_partial[2 * SPLITK * BT * N_HID];        // per-group split-K partials
__device__ float g_state[BATCH * N_HID];                    // hidden state (fp32)
__device__ unsigned g_cnt2[2];                              // per-group barrier arrivals
__device__ unsigned g_gen2[2];                              // per-group barrier generation
__device__ unsigned g_cnt_all;                              // joint barrier arrivals
__device__ unsigned g_gen_all;                              // joint barrier generation

// -------- packed f32x2 FMA --------
__device__ __forceinline__ unsigned long long ffma2(unsigned long long a,
                                                    unsigned long long b,
                                                    unsigned long long c) {
    unsigned long long d;
    asm("fma.rn.f32x2 %0, %1, %2, %3;" : "=l"(d) : "l"(a), "l"(b), "l"(c));
    return d;
}
__device__ __forceinline__ float lo32(unsigned long long v) {
    return __uint_as_float((unsigned)(v & 0xffffffffull));
}
__device__ __forceinline__ float hi32(unsigned long long v) {
    return __uint_as_float((unsigned)(v >> 32));
}

// -------- software barrier over nc CTAs (monotonic targets) --------
__device__ __forceinline__ void gbar(unsigned* cnt, unsigned* gen, unsigned nc, unsigned target) {
    __syncthreads();
    if (threadIdx.x == 0) {
        __threadfence();
        unsigned old = atomicAdd(cnt, 1u);
        if (old == nc * target - 1u) {
            asm volatile("st.release.gpu.u32 [%0], %1;" :: "l"(gen), "r"(target) : "memory");
        } else {
            unsigned v;
            do {
                asm volatile("ld.acquire.gpu.u32 %0, [%1];" : "=r"(v) : "l"(gen) : "memory");
            } while (v < target);
        }
    }
    __syncthreads();
}

// ==================== persistent-kernel tile helpers ====================

__device__ __forceinline__ void sts64(float2* p, float a, float b) {
    asm volatile("st.shared.v2.f32 [%0], {%1, %2};"
                 :: "l"(__cvta_generic_to_shared(p)), "f"(a), "f"(b) : "memory");
}

// Load a [ROWS x 128 floats] tile into smem S[row][kp], pitch LDP. TPC=128 threads:
// warp = one 512B row (coalesced LDG.128); 2x STS.64 each.
template <int ROWS>
__device__ __forceinline__ void load_tile128(float2 (*S)[LDP], const float* __restrict__ src,
                                             size_t rowbase, int ld, int k0, int tid) {
#pragma unroll
    for (int it = 0; it < ROWS / 4; it++) {
        int f   = it * TPC + tid;   // float4 index, ROWS*32 total
        int row = f >> 5;           // 32 float4 per row
        int fq  = f & 31;
        const float4 v = *reinterpret_cast<const float4*>(
            src + (rowbase + (size_t)row) * (size_t)ld + k0 + fq * 4);
        sts64(&S[row][2 * fq + 0], v.x, v.y);
        sts64(&S[row][2 * fq + 1], v.z, v.w);
    }
}

// 4x8 per-thread outer product over KC=128. ty = tid>>3 (rows ty*4+i, 0..63),
// tx = tid&7 (h = 2tx+16jj+p, 0..63). Bank-audited conflict-free at pitch 65.
__device__ __forceinline__ void compute128(const float2 (*Ss)[LDP], const float2 (*Ws)[LDP],
                                           int ty, int tx, unsigned long long (*acc)[8]) {
#pragma unroll
    for (int kp = 0; kp < KP; kp++) {
        unsigned long long s[4], w[8];
#pragma unroll
        for (int i = 0; i < 4; i++)
            s[i] = *reinterpret_cast<const unsigned long long*>(&Ss[ty * 4 + i][kp]);
#pragma unroll
        for (int jj = 0; jj < 4; jj++) {
            w[2 * jj + 0] = *reinterpret_cast<const unsigned long long*>(&Ws[2 * tx + 16 * jj + 0][kp]);
            w[2 * jj + 1] = *reinterpret_cast<const unsigned long long*>(&Ws[2 * tx + 16 * jj + 1][kp]);
        }
#pragma unroll
        for (int i = 0; i < 4; i++)
#pragma unroll
            for (int q = 0; q < 8; q++)
                acc[i][q] = ffma2(s[i], w[q], acc[i][q]);
    }
}

// Epilogue: rows ty*4+i (local), cols hbase + 16jj + {0,1}, STG.64.
__device__ __forceinline__ void store_acc(float* __restrict__ po, int ldo, int hbase,
                                          int ty, unsigned long long (*acc)[8]) {
#pragma unroll
    for (int i = 0; i < 4; i++) {
        float* prow = po + (size_t)(ty * 4 + i) * ldo + hbase;
#pragma unroll
        for (int jj = 0; jj < 4; jj++) {
            float2 v = make_float2(lo32(acc[i][2 * jj]) + hi32(acc[i][2 * jj]),
                                   lo32(acc[i][2 * jj + 1]) + hi32(acc[i][2 * jj + 1]));
            *reinterpret_cast<float2*>(prow + 16 * jj) = v;
        }
    }
}

// ==================== kernels ====================

__global__ __launch_bounds__(256, 1) void init_kernel() {
    const int idx = blockIdx.x * 256 + threadIdx.x;   // float4 over 512KB state
    reinterpret_cast<float4*>(g_state)[idx] = make_float4(0.f, 0.f, 0.f, 0.f);
    if (idx == 0) {
        g_cnt2[0] = 0u; g_cnt2[1] = 0u;
        g_gen2[0] = 0u; g_gen2[1] = 0u;
        g_cnt_all = 0u; g_gen_all = 0u;
    }
}

// -------- xproj (R7-exact, known good; one-time ~250us) --------
__device__ __forceinline__ void load_tile_f32(float2 (*S)[128], const float* __restrict__ src,
                                              size_t rowbase, int ld, int k0, int tid) {
#pragma unroll
    for (int r = 0; r < 4; r++) {
        int f = r * 256 + tid;
        int row = f >> 3, fq = f & 7;
        const float4 v = *reinterpret_cast<const float4*>(
            src + (rowbase + (size_t)row) * (size_t)ld + k0 + fq * 4);
        S[2 * fq + 0][row] = make_float2(v.x, v.y);
        S[2 * fq + 1][row] = make_float2(v.z, v.w);
    }
}

__device__ __forceinline__ void compute_chunk32(const float2 (*Ss)[128], const float2 (*Ws)[128],
                                                int ty, int tx, unsigned long long (*acc)[8]) {
#pragma unroll
    for (int kp = 0; kp < KPAIRS; kp++) {
        unsigned long long s[8], w[8];
        const ulonglong2* sp = reinterpret_cast<const ulonglong2*>(&Ss[kp][ty * 8]);
#pragma unroll
        for (int q = 0; q < 4; q++) {
            ulonglong2 v = sp[q];
            s[2 * q + 0] = v.x; s[2 * q + 1] = v.y;
        }
#pragma unroll
        for (int j = 0; j < 8; j++)
            w[j] = *reinterpret_cast<const unsigned long long*>(&Ws[kp][tx + 16 * j]);
#pragma unroll
        for (int i = 0; i < 8; i++)
#pragma unroll
            for (int j = 0; j < 8; j++)
                acc[i][j] = ffma2(s[i], w[j], acc[i][j]);
    }
}

__global__ __launch_bounds__(256, 1) void xproj_kernel(const float* __restrict__ x,
                                                       const float* __restrict__ W_ih,
                                                       const float* __restrict__ b_ih,
                                                       const float* __restrict__ b_hh) {
    __shared__ alignas(16) float2 Ss[KPAIRS][128];
    __shared__ alignas(16) float2 Ws[KPAIRS][128];
    const int tid = threadIdx.x;
    const int tx = tid & 15, ty = tid >> 4;
    const int mtile = blockIdx.x, htile = blockIdx.y;

    unsigned long long acc[8][8];
#pragma unroll
    for (int i = 0; i < 8; i++)
#pragma unroll
        for (int j = 0; j < 8; j++) acc[i][j] = 0ull;

    for (int c = 0; c < N_INP / KC; c++) {
        const int k0 = c * KC;
        load_tile_f32(Ss, x,    (size_t)mtile * 128, N_INP, k0, tid);
        load_tile_f32(Ws, W_ih, (size_t)htile * 128, N_INP, k0, tid);
        __syncthreads();
        compute_chunk32(Ss, Ws, ty, tx, acc);
        __syncthreads();
    }

    const int b0 = ty * 8;
    const int hbase = htile * 128 + tx;
    float bias[8];
#pragma unroll
    for (int j = 0; j < 8; j++) {
        const int h = hbase + 16 * j;
        bias[j] = b_ih[h] + b_hh[h];
    }
#pragma unroll
    for (int i = 0; i < 8; i++) {
        const size_t row = ((size_t)mtile * 128 + b0 + i) * N_HID;
#pragma unroll
        for (int j = 0; j < 8; j++)
            g_xp[row + hbase + 16 * j] = lo32(acc[i][j]) + hi32(acc[i][j]) + bias[j];
    }
}

// -------- two-group persistent recurrence + readout --------
// Dynamic smem per CTA: Sp[64][65] + Wp[64][65] float2 = 66560 B (2 CTAs/SM = 133120 B).
#define SM_TOTAL (2 * BT * LDP * 8)

__global__ __launch_bounds__(TPC, 2) void rnn_persistent(const float* __restrict__ W_hh,
                                                         const float* __restrict__ W_ro,
                                                         const float* __restrict__ b_ro,
                                                         float* __restrict__ out) {
    extern __shared__ char smem[];
    float2 (*Sp)[LDP] = reinterpret_cast<float2 (*)[LDP]>(smem);
    float2 (*Wp)[LDP] = reinterpret_cast<float2 (*)[LDP]>(smem + BT * LDP * 8);

    const int tid = threadIdx.x;
    const int tx = tid & 7, ty = tid >> 3;
    const int grp = blockIdx.x >> 7;          // 0: bids 0-127, 1: bids 128-255
    const int cg  = blockIdx.x & 127;         // CTA index within group
    const int htile = cg >> 3;                // 0..15 (64-wide h tiles)
    const int ks = cg & 7;                    // 0..7  (128-wide k slices)
    const int hbase = htile * 64 + 2 * tx;
    const size_t sbase = (size_t)grp * BT;    // this group's state row base
    const int idxg = cg * TPC + tid;          // f4 index within group's 16384-f4 state block
    unsigned* cnt = &g_cnt2[grp];
    unsigned* gen = &g_gen2[grp];
    unsigned target = 0;

    // Persist this CTA's W_hh tile (h = htile*64.., k = ks*128..) for all steps.
    load_tile128<BT>(Wp, W_hh, (size_t)htile * 64, N_HID, ks * KSLICE, tid);
    __syncthreads();

    for (int t = 0; t < T_STEPS; t++) {
        // ---- phase A: partial[grp][ks][b_local][h] = state_grp @ W_hh^T (k-slice) ----
        load_tile128<BT>(Sp, g_state, sbase, N_HID, ks * KSLICE, tid);
        __syncthreads();

        // Anti-phase gate: group1 computes only after group0 arrived at its bar-1
        // of this step. Group0 never waits on group1 -> deadlock-free.
        if (grp == 1) {
            if (tid == 0) {
                const unsigned need = 2u * (unsigned)t + 1u;
                unsigned v;
                do {
                    asm volatile("ld.acquire.gpu.u32 %0, [%1];"
                                 : "=r"(v) : "l"(&g_gen2[0]) : "memory");
                } while (v < need);
            }
            __syncthreads();
        }

        unsigned long long acc[4][8];
#pragma unroll
        for (int i = 0; i < 4; i++)
#pragma unroll
            for (int q = 0; q < 8; q++) acc[i][q] = 0ull;

        compute128(Sp, Wp, ty, tx, acc);

        store_acc(g_partial + (size_t)(grp * SPLITK + ks) * BT * N_HID,
                  N_HID, hbase, ty, acc);

        // Prefetch xp[t] (independent of the barrier).
        const float4 xpv = reinterpret_cast<const float4*>(
            g_xp + (size_t)t * BATCH * N_HID)[grp * 16384 + idxg];

        gbar(cnt, gen, GCTA, ++target);

        // ---- phase B: state rows of this group = tanh(xp + sum_ks partial) ----
        {
            float4 s = xpv;
#pragma unroll
            for (int k2 = 0; k2 < SPLITK; k2++) {
                const float4 p = reinterpret_cast<const float4*>(
                    g_partial + (size_t)(grp * SPLITK + k2) * BT * N_HID)[idxg];
                s.x += p.x; s.y += p.y; s.z += p.z; s.w += p.w;
            }
            reinterpret_cast<float4*>(g_state)[grp * 16384 + idxg] =
                make_float4(tanhf(s.x), tanhf(s.y), tanhf(s.z), tanhf(s.w));
        }
        gbar(cnt, gen, GCTA, ++target);
    }

    // ---- joint barrier: both groups' final states visible ----
    gbar(&g_cnt_all, &g_gen_all, 2 * GCTA, 1);

    // ---- readout: out = state @ W_ro^T + b_ro (32 CTAs: 2 btile x 2 otile x 8 ks) ----
    if (blockIdx.x < 32) {
        const int bt2 = blockIdx.x & 1;        // batch half
        const int h2  = (blockIdx.x >> 1) & 1; // output half (64 wide)
        const int ks2 = blockIdx.x >> 2;       // 0..7
        load_tile128<BT>(Wp, W_ro,    (size_t)h2 * 64,  N_HID, ks2 * KSLICE, tid);
        load_tile128<BT>(Sp, g_state, (size_t)bt2 * 64, N_HID, ks2 * KSLICE, tid);
        __syncthreads();

        unsigned long long acc[4][8];
#pragma unroll
        for (int i = 0; i < 4; i++)
#pragma unroll
            for (int q = 0; q < 8; q++) acc[i][q] = 0ull;

        compute128(Sp, Wp, ty, tx, acc);

        store_acc(g_partial + (size_t)ks2 * BATCH * N_OUT + (size_t)bt2 * 64 * N_OUT,
                  N_OUT, h2 * 64 + 2 * tx, ty, acc);
    }
    gbar(&g_cnt_all, &g_gen_all, 2 * GCTA, 2);

    if (blockIdx.x < 32) {
        const int idx = blockIdx.x * TPC + tid;   // f4 over 128x128 output (4096)
        float4 s = make_float4(0.f, 0.f, 0.f, 0.f);
#pragma unroll
        for (int k2 = 0; k2 < SPLITK; k2++) {
            const float4 p = reinterpret_cast<const float4*>(
                g_partial + (size_t)k2 * BATCH * N_OUT)[idx];
            s.x += p.x; s.y += p.y; s.z += p.z; s.w += p.w;
        }
        const int o0 = (idx * 4) & (N_OUT - 1);
        const float4 bb = *reinterpret_cast<const float4*>(b_ro + o0);
        s.x += bb.x; s.y += bb.y; s.z += bb.z; s.w += bb.w;
        reinterpret_cast<float4*>(out)[idx] = s;
    }
}

// -------- launch (3 graph nodes) --------
extern "C" void kernel_launch(void* const* d_in, const int* in_sizes, int n_in,
                              void* d_out, int out_size) {
    const float* x    = (const float*)d_in[0];   // [512,128,256]
    const float* W_ih = (const float*)d_in[1];   // [1024,256]
    const float* W_hh = (const float*)d_in[2];   // [1024,1024]
    const float* b_ih = (const float*)d_in[3];   // [1024]
    const float* b_hh = (const float*)d_in[4];   // [1024]
    const float* W_ro = (const float*)d_in[5];   // [128,1024]
    const float* b_ro = (const float*)d_in[6];   // [128]
    float* out = (float*)d_out;                  // [128,128]

    (void)in_sizes; (void)n_in; (void)out_size;

    // Idempotent, capture-safe.
    cudaFuncSetAttribute(rnn_persistent,
                         cudaFuncAttributeMaxDynamicSharedMemorySize, SM_TOTAL);

    init_kernel<<<128, 256>>>();
    xproj_kernel<<<dim3(T_STEPS * BATCH / 128, N_HID / 128), 256>>>(x, W_ih, b_ih, b_hh);
    rnn_persistent<<<2 * GCTA, TPC, SM_TOTAL>>>(W_hh, W_ro, b_ro, out);
}

// round 15
// speedup vs baseline: 1.7599x; 1.7599x over previous
#include <cuda_runtime.h>
#include <cstdint>
#include <cstddef>

// Problem constants
#define T_STEPS 512
#define BATCH   128
#define N_INP   256
#define N_HID   1024
#define N_OUT   128

#define SPLITK  8                  // k-split (K=1024 -> 128/slice)
#define KSLICE  128
#define KP      (KSLICE / 2)       // 64 float2 k-pairs
#define NCTA    128                // persistent grid (1 CTA/SM, co-resident)
#define TPC     256
#define LDP     65                 // padded row pitch (float2): 520B rows

// xproj tiling (R7-exact)
#define KC      32
#define KPAIRS  (KC / 2)

// -------- scratch (device globals; no runtime allocation allowed) --------
__device__ float g_xp[(size_t)T_STEPS * BATCH * N_HID];       // input projection (+biases)
__device__ float g_part2[2][SPLITK * BATCH * N_HID];          // ping-pong split-K partials
__device__ float g_state2[2][BATCH * N_HID];                  // ping-pong hidden state
__device__ unsigned g_pdone[16];   // per-htile partial-ready counters (monotonic)
__device__ unsigned g_sdone[8];    // per-slice state-ready counters (monotonic)
__device__ unsigned g_cnt_all;     // final joint barrier arrivals
__device__ unsigned g_gen_all;     // final joint barrier generation

// -------- packed f32x2 FMA (full-rate fp32) --------
__device__ __forceinline__ unsigned long long ffma2(unsigned long long a,
                                                    unsigned long long b,
                                                    unsigned long long c) {
    unsigned long long d;
    asm("fma.rn.f32x2 %0, %1, %2, %3;" : "=l"(d) : "l"(a), "l"(b), "l"(c));
    return d;
}
__device__ __forceinline__ float lo32(unsigned long long v) {
    return __uint_as_float((unsigned)(v & 0xffffffffull));
}
__device__ __forceinline__ float hi32(unsigned long long v) {
    return __uint_as_float((unsigned)(v >> 32));
}

// -------- sync primitives --------
__device__ __forceinline__ void poll_ge(unsigned* p, unsigned target) {
    unsigned v;
    do {
        asm volatile("ld.acquire.gpu.u32 %0, [%1];" : "=r"(v) : "l"(p) : "memory");
    } while (v < target);
}

// full barrier over nc CTAs (used once before readout)
__device__ __forceinline__ void gbar(unsigned* cnt, unsigned* gen, unsigned nc, unsigned target) {
    __syncthreads();
    if (threadIdx.x == 0) {
        __threadfence();
        unsigned old = atomicAdd(cnt, 1u);
        if (old == nc * target - 1u) {
            asm volatile("st.release.gpu.u32 [%0], %1;" :: "l"(gen), "r"(target) : "memory");
        } else {
            poll_ge(gen, target);
        }
    }
    __syncthreads();
}

// ==================== tile helpers (row-major, padded; R13-proven) ====================

__device__ __forceinline__ void sts64(float2* p, float a, float b) {
    asm volatile("st.shared.v2.f32 [%0], {%1, %2};"
                 :: "l"(__cvta_generic_to_shared(p)), "f"(a), "f"(b) : "memory");
}

// Load a [ROWS x 128 floats] tile into smem S[row][kp], pitch LDP. 256 threads.
template <int ROWS>
__device__ __forceinline__ void load_tile128(float2 (*S)[LDP], const float* __restrict__ src,
                                             size_t rowbase, int ld, int k0, int tid) {
#pragma unroll
    for (int it = 0; it < ROWS / 8; it++) {
        int f   = it * 256 + tid;
        int row = f >> 5;           // 32 float4 per row
        int fq  = f & 31;
        const float4 v = *reinterpret_cast<const float4*>(
            src + (rowbase + (size_t)row) * (size_t)ld + k0 + fq * 4);
        sts64(&S[row][2 * fq + 0], v.x, v.y);
        sts64(&S[row][2 * fq + 1], v.z, v.w);
    }
}

// 4x8 per-thread outer product over KC=128 (bank-audited conflict-free at pitch 65).
__device__ __forceinline__ void compute128(const float2 (*Ss)[LDP], const float2 (*Ws)[LDP],
                                           int ty, int tx, unsigned long long (*acc)[8]) {
#pragma unroll
    for (int kp = 0; kp < KP; kp++) {
        unsigned long long s[4], w[8];
#pragma unroll
        for (int i = 0; i < 4; i++)
            s[i] = *reinterpret_cast<const unsigned long long*>(&Ss[ty * 4 + i][kp]);
#pragma unroll
        for (int jj = 0; jj < 4; jj++) {
            w[2 * jj + 0] = *reinterpret_cast<const unsigned long long*>(&Ws[2 * tx + 16 * jj + 0][kp]);
            w[2 * jj + 1] = *reinterpret_cast<const unsigned long long*>(&Ws[2 * tx + 16 * jj + 1][kp]);
        }
#pragma unroll
        for (int i = 0; i < 4; i++)
#pragma unroll
            for (int q = 0; q < 8; q++)
                acc[i][q] = ffma2(s[i], w[q], acc[i][q]);
    }
}

// Epilogue: rows ty*4+i, cols hbase + 16jj + {0,1}, STG.64.
__device__ __forceinline__ void store_acc(float* __restrict__ po, int ldo, int hbase,
                                          int ty, unsigned long long (*acc)[8]) {
#pragma unroll
    for (int i = 0; i < 4; i++) {
        float* prow = po + (size_t)(ty * 4 + i) * ldo + hbase;
#pragma unroll
        for (int jj = 0; jj < 4; jj++) {
            float2 v = make_float2(lo32(acc[i][2 * jj]) + hi32(acc[i][2 * jj]),
                                   lo32(acc[i][2 * jj + 1]) + hi32(acc[i][2 * jj + 1]));
            *reinterpret_cast<float2*>(prow + 16 * jj) = v;
        }
    }
}

// ==================== kernels ====================

__global__ void init_kernel() {
    if (threadIdx.x < 16) g_pdone[threadIdx.x] = 0u;
    if (threadIdx.x < 8)  g_sdone[threadIdx.x] = 0u;
    if (threadIdx.x == 0) { g_cnt_all = 0u; g_gen_all = 0u; }
}

// -------- xproj (R7-exact, known good; one-time ~250us) --------
__device__ __forceinline__ void load_tile_f32(float2 (*S)[128], const float* __restrict__ src,
                                              size_t rowbase, int ld, int k0, int tid) {
#pragma unroll
    for (int r = 0; r < 4; r++) {
        int f = r * 256 + tid;
        int row = f >> 3, fq = f & 7;
        const float4 v = *reinterpret_cast<const float4*>(
            src + (rowbase + (size_t)row) * (size_t)ld + k0 + fq * 4);
        S[2 * fq + 0][row] = make_float2(v.x, v.y);
        S[2 * fq + 1][row] = make_float2(v.z, v.w);
    }
}

__device__ __forceinline__ void compute_chunk32(const float2 (*Ss)[128], const float2 (*Ws)[128],
                                                int ty, int tx, unsigned long long (*acc)[8]) {
#pragma unroll
    for (int kp = 0; kp < KPAIRS; kp++) {
        unsigned long long s[8], w[8];
        const ulonglong2* sp = reinterpret_cast<const ulonglong2*>(&Ss[kp][ty * 8]);
#pragma unroll
        for (int q = 0; q < 4; q++) {
            ulonglong2 v = sp[q];
            s[2 * q + 0] = v.x; s[2 * q + 1] = v.y;
        }
#pragma unroll
        for (int j = 0; j < 8; j++)
            w[j] = *reinterpret_cast<const unsigned long long*>(&Ws[kp][tx + 16 * j]);
#pragma unroll
        for (int i = 0; i < 8; i++)
#pragma unroll
            for (int j = 0; j < 8; j++)
                acc[i][j] = ffma2(s[i], w[j], acc[i][j]);
    }
}

__global__ __launch_bounds__(256, 1) void xproj_kernel(const float* __restrict__ x,
                                                       const float* __restrict__ W_ih,
                                                       const float* __restrict__ b_ih,
                                                       const float* __restrict__ b_hh) {
    __shared__ alignas(16) float2 Ss[KPAIRS][128];
    __shared__ alignas(16) float2 Ws[KPAIRS][128];
    const int tid = threadIdx.x;
    const int tx = tid & 15, ty = tid >> 4;
    const int mtile = blockIdx.x, htile = blockIdx.y;

    unsigned long long acc[8][8];
#pragma unroll
    for (int i = 0; i < 8; i++)
#pragma unroll
        for (int j = 0; j < 8; j++) acc[i][j] = 0ull;

    for (int c = 0; c < N_INP / KC; c++) {
        const int k0 = c * KC;
        load_tile_f32(Ss, x,    (size_t)mtile * 128, N_INP, k0, tid);
        load_tile_f32(Ws, W_ih, (size_t)htile * 128, N_INP, k0, tid);
        __syncthreads();
        compute_chunk32(Ss, Ws, ty, tx, acc);
        __syncthreads();
    }

    const int b0 = ty * 8;
    const int hbase = htile * 128 + tx;
    float bias[8];
#pragma unroll
    for (int j = 0; j < 8; j++) {
        const int h = hbase + 16 * j;
        bias[j] = b_ih[h] + b_hh[h];
    }
#pragma unroll
    for (int i = 0; i < 8; i++) {
        const size_t row = ((size_t)mtile * 128 + b0 + i) * N_HID;
#pragma unroll
        for (int j = 0; j < 8; j++)
            g_xp[row + hbase + 16 * j] = lo32(acc[i][j]) + hi32(acc[i][j]) + bias[j];
    }
}

// -------- persistent recurrence, fine-grained sync --------
// Dynamic smem: Sp[128][65] + Wp[64][65] float2 = 99840 B.
#define SM_SP_BYTES (128 * LDP * 8)
#define SM_TOTAL    (SM_SP_BYTES + 64 * LDP * 8)

__global__ __launch_bounds__(TPC, 1) void rnn_persistent(const float* __restrict__ W_hh,
                                                         const float* __restrict__ W_ro,
                                                         const float* __restrict__ b_ro,
                                                         float* __restrict__ out) {
    extern __shared__ char smem[];
    float2 (*Sp)[LDP] = reinterpret_cast<float2 (*)[LDP]>(smem);
    float2 (*Wp)[LDP] = reinterpret_cast<float2 (*)[LDP]>(smem + SM_SP_BYTES);

    const int tid = threadIdx.x;
    const int tx = tid & 7, ty = tid >> 3;
    const int h = blockIdx.x >> 3;       // htile 0..15 (64-wide h tiles)
    const int j = blockIdx.x & 7;        // k-slice 0..7 (128-wide)
    const int hbase = h * 64 + 2 * tx;
    // phase-B mapping: this CTA reduces batches [16j,16j+16), cols [64h,64h+64)
    const int b_loc = tid >> 4;          // 0..15
    const int c4    = tid & 15;          // 0..15 (f4 within 64 cols)
    const int bb    = j * 16 + b_loc;    // batch row
    const int f4col = h * 16 + c4;       // f4 col within N_HID (256 f4)

    // Persist this CTA's W_hh tile (h = h*64.., k = j*128..) for all steps.
    load_tile128<64>(Wp, W_hh, (size_t)h * 64, N_HID, j * KSLICE, tid);
    // Prologue: state(t=0) = 0 -> zero Sp directly (gmem state never read at t=0).
    {
        float2* p = &Sp[0][0];
        for (int i = tid; i < 128 * LDP; i += TPC) p[i] = make_float2(0.f, 0.f);
    }
    __syncthreads();

    for (int t = 0; t < T_STEPS; t++) {
        const int par = t & 1;
        // ---- phase A: partial[par][j][b][h-range] = state-slice-j @ W_hh^T ----
        unsigned long long acc[4][8];
#pragma unroll
        for (int i = 0; i < 4; i++)
#pragma unroll
            for (int q = 0; q < 8; q++) acc[i][q] = 0ull;

        compute128(Sp, Wp, ty, tx, acc);
        store_acc(g_part2[par] + (size_t)j * BATCH * N_HID, N_HID, hbase, ty, acc);

        // Prefetch xp for phase B (known early, independent of sync).
        const float4 xpv = reinterpret_cast<const float4*>(g_xp)
            [((size_t)t * BATCH + bb) * (N_HID / 4) + f4col];

        // ---- sync 1: wait for the 8 CTAs producing partials for my h-columns ----
        __syncthreads();
        if (tid == 0) {
            __threadfence();
            atomicAdd(&g_pdone[h], 1u);
            poll_ge(&g_pdone[h], 8u * (unsigned)(t + 1));
        }
        __syncthreads();

        // ---- phase B: state[par^1][bb][64h..64h+64) = tanh(xp + sum partials) ----
        {
            float4 s = xpv;
            const float4* pb = reinterpret_cast<const float4*>(g_part2[par]);
#pragma unroll
            for (int k2 = 0; k2 < SPLITK; k2++) {
                const float4 p = pb[((size_t)k2 * BATCH + bb) * (N_HID / 4) + f4col];
                s.x += p.x; s.y += p.y; s.z += p.z; s.w += p.w;
            }
            reinterpret_cast<float4*>(g_state2[par ^ 1])
                [(size_t)bb * (N_HID / 4) + f4col] =
                make_float4(tanhf(s.x), tanhf(s.y), tanhf(s.z), tanhf(s.w));
        }

        // ---- sync 2: slice j ready when its 16 producers (htiles 2j,2j+1) done ----
        __syncthreads();
        if (tid == 0) {
            __threadfence();
            atomicAdd(&g_sdone[h >> 1], 1u);
            poll_ge(&g_sdone[j], 16u * (unsigned)(t + 1));
        }
        __syncthreads();

        // ---- load next state slice j into smem ----
        load_tile128<128>(Sp, g_state2[par ^ 1], 0, N_HID, j * KSLICE, tid);
        __syncthreads();
    }

    // ---- final joint barrier, then readout (state parity 0 after 512 steps) ----
    gbar(&g_cnt_all, &g_gen_all, NCTA, 1);

    if (blockIdx.x < 16) {
        const int h2 = blockIdx.x >> 3;      // output half (64 wide)
        const int ks2 = blockIdx.x & 7;      // k-slice
        load_tile128<64>(Wp, W_ro, (size_t)h2 * 64, N_HID, ks2 * KSLICE, tid);
        load_tile128<128>(Sp, g_state2[0], 0, N_HID, ks2 * KSLICE, tid);
        __syncthreads();

        unsigned long long acc[4][8];
#pragma unroll
        for (int i = 0; i < 4; i++)
#pragma unroll
            for (int q = 0; q < 8; q++) acc[i][q] = 0ull;

        compute128(Sp, Wp, ty, tx, acc);
        store_acc(g_part2[0] + (size_t)ks2 * BATCH * N_OUT, N_OUT,
                  h2 * 64 + 2 * tx, ty, acc);
    }
    gbar(&g_cnt_all, &g_gen_all, NCTA, 2);

    if (blockIdx.x < 16) {
        const int idx = blockIdx.x * TPC + tid;   // f4 over 128x128 output
        float4 s = make_float4(0.f, 0.f, 0.f, 0.f);
#pragma unroll
        for (int k2 = 0; k2 < SPLITK; k2++) {
            const float4 p = reinterpret_cast<const float4*>(
                g_part2[0] + (size_t)k2 * BATCH * N_OUT)[idx];
            s.x += p.x; s.y += p.y; s.z += p.z; s.w += p.w;
        }
        const int o0 = (idx * 4) & (N_OUT - 1);
        const float4 bb2 = *reinterpret_cast<const float4*>(b_ro + o0);
        s.x += bb2.x; s.y += bb2.y; s.z += bb2.z; s.w += bb2.w;
        reinterpret_cast<float4*>(out)[idx] = s;
    }
}

// -------- launch (3 graph nodes) --------
extern "C" void kernel_launch(void* const* d_in, const int* in_sizes, int n_in,
                              void* d_out, int out_size) {
    const float* x    = (const float*)d_in[0];   // [512,128,256]
    const float* W_ih = (const float*)d_in[1];   // [1024,256]
    const float* W_hh = (const float*)d_in[2];   // [1024,1024]
    const float* b_ih = (const float*)d_in[3];   // [1024]
    const float* b_hh = (const float*)d_in[4];   // [1024]
    const float* W_ro = (const float*)d_in[5];   // [128,1024]
    const float* b_ro = (const float*)d_in[6];   // [128]
    float* out = (float*)d_out;                  // [128,128]

    (void)in_sizes; (void)n_in; (void)out_size;

    // Idempotent, capture-safe.
    cudaFuncSetAttribute(rnn_persistent,
                         cudaFuncAttributeMaxDynamicSharedMemorySize, SM_TOTAL);

    init_kernel<<<1, 32>>>();
    xproj_kernel<<<dim3(T_STEPS * BATCH / 128, N_HID / 128), 256>>>(x, W_ih, b_ih, b_hh);
    rnn_persistent<<<NCTA, TPC, SM_TOTAL>>>(W_hh, W_ro, b_ro, out);
}

// round 16
// speedup vs baseline: 1.7772x; 1.0099x over previous
#include <cuda_runtime.h>
#include <cstdint>
#include <cstddef>

// Problem constants
#define T_STEPS 512
#define BATCH   128
#define N_INP   256
#define N_HID   1024
#define N_OUT   128

#define SPLITK  8                  // k-split (K=1024 -> 128/slice)
#define KSLICE  128
#define KP      (KSLICE / 2)       // 64 float2 k-pairs
#define NCTA    128                // persistent grid (1 CTA/SM, co-resident)
#define TPC     256
#define LDP     65                 // row pitch (float2); +(row&1) skew -> 16B-aligned rows

#define SP_F2   (128 * LDP + 2)    // Sp float2 count (incl. skew pad)
#define WP_F2   (64 * LDP + 2)     // Wp float2 count

// xproj tiling (R7-exact)
#define KC      32
#define KPAIRS  (KC / 2)

// -------- scratch (device globals; no runtime allocation allowed) --------
__device__ float g_xp[(size_t)T_STEPS * BATCH * N_HID];       // input projection (+biases)
__device__ float g_part2[2][SPLITK * BATCH * N_HID];          // ping-pong split-K partials
__device__ float g_state2[2][BATCH * N_HID];                  // ping-pong hidden state
__device__ unsigned g_pdone[16];   // per-htile partial-ready counters (monotonic)
__device__ unsigned g_sdone[8];    // per-slice state-ready counters (monotonic)
__device__ unsigned g_cnt_all;     // final joint barrier arrivals
__device__ unsigned g_gen_all;     // final joint barrier generation

// -------- packed f32x2 FMA (full-rate fp32) --------
__device__ __forceinline__ unsigned long long ffma2(unsigned long long a,
                                                    unsigned long long b,
                                                    unsigned long long c) {
    unsigned long long d;
    asm("fma.rn.f32x2 %0, %1, %2, %3;" : "=l"(d) : "l"(a), "l"(b), "l"(c));
    return d;
}
__device__ __forceinline__ float lo32(unsigned long long v) {
    return __uint_as_float((unsigned)(v & 0xffffffffull));
}
__device__ __forceinline__ float hi32(unsigned long long v) {
    return __uint_as_float((unsigned)(v >> 32));
}

// -------- fast tanh: 1 - 2/(exp2(2x*log2e)+1); ex2/rcp approx (~2^-21 rel err) --------
__device__ __forceinline__ float fast_tanh(float x) {
    float e, r;
    float t = x * 2.885390081777927f;   // 2*log2(e)
    asm("ex2.approx.f32 %0, %1;" : "=f"(e) : "f"(t));
    asm("rcp.approx.f32 %0, %1;" : "=f"(r) : "f"(e + 1.0f));
    return fmaf(-2.0f, r, 1.0f);
}

// -------- sync primitives --------
__device__ __forceinline__ void poll_ge(unsigned* p, unsigned target) {
    unsigned v;
    do {
        asm volatile("ld.acquire.gpu.u32 %0, [%1];" : "=r"(v) : "l"(p) : "memory");
    } while (v < target);
}

__device__ __forceinline__ void gbar(unsigned* cnt, unsigned* gen, unsigned nc, unsigned target) {
    __syncthreads();
    if (threadIdx.x == 0) {
        __threadfence();
        unsigned old = atomicAdd(cnt, 1u);
        if (old == nc * target - 1u) {
            asm volatile("st.release.gpu.u32 [%0], %1;" :: "l"(gen), "r"(target) : "memory");
        } else {
            poll_ge(gen, target);
        }
    }
    __syncthreads();
}

// ==================== tile helpers (skewed row-major) ====================
// Row base (float2 units): row*LDP + (row&1)  -> every row 16B-aligned.

// Load a [ROWS x 128 floats] tile into smem, one STS.128 per float4 (conflict-free:
// lanes of a warp cover one 512B row contiguously). 256 threads.
template <int ROWS>
__device__ __forceinline__ void load_tile128(float2* S, const float* __restrict__ src,
                                             size_t rowbase, int ld, int k0, int tid) {
#pragma unroll
    for (int it = 0; it < ROWS / 8; it++) {
        int f   = it * 256 + tid;
        int row = f >> 5;           // 32 float4 per row
        int fq  = f & 31;
        const float4 v = *reinterpret_cast<const float4*>(
            src + (rowbase + (size_t)row) * (size_t)ld + k0 + fq * 4);
        *reinterpret_cast<float4*>(S + (size_t)row * LDP + (row & 1) + 2 * fq) = v;
    }
}

// 4x8 per-thread outer product over KC=128 (bank-audited conflict-free under skew).
__device__ __forceinline__ void compute128(const float2* Ss, const float2* Ws,
                                           int ty, int tx, unsigned long long (*acc)[8]) {
#pragma unroll
    for (int kp = 0; kp < KP; kp++) {
        unsigned long long s[4], w[8];
#pragma unroll
        for (int i = 0; i < 4; i++)
            s[i] = *reinterpret_cast<const unsigned long long*>(
                Ss + (size_t)(ty * 4 + i) * LDP + (i & 1) + kp);
#pragma unroll
        for (int jj = 0; jj < 4; jj++) {
#pragma unroll
            for (int p = 0; p < 2; p++) {
                const int row = 2 * tx + 16 * jj + p;
                w[2 * jj + p] = *reinterpret_cast<const unsigned long long*>(
                    Ws + (size_t)row * LDP + p + kp);
            }
        }
#pragma unroll
        for (int i = 0; i < 4; i++)
#pragma unroll
            for (int q = 0; q < 8; q++)
                acc[i][q] = ffma2(s[i], w[q], acc[i][q]);
    }
}

// Epilogue: rows ty*4+i, cols hbase + 16jj + {0,1}, STG.64.
__device__ __forceinline__ void store_acc(float* __restrict__ po, int ldo, int hbase,
                                          int ty, unsigned long long (*acc)[8]) {
#pragma unroll
    for (int i = 0; i < 4; i++) {
        float* prow = po + (size_t)(ty * 4 + i) * ldo + hbase;
#pragma unroll
        for (int jj = 0; jj < 4; jj++) {
            float2 v = make_float2(lo32(acc[i][2 * jj]) + hi32(acc[i][2 * jj]),
                                   lo32(acc[i][2 * jj + 1]) + hi32(acc[i][2 * jj + 1]));
            *reinterpret_cast<float2*>(prow + 16 * jj) = v;
        }
    }
}

// ==================== kernels ====================

__global__ void init_kernel() {
    if (threadIdx.x < 16) g_pdone[threadIdx.x] = 0u;
    if (threadIdx.x < 8)  g_sdone[threadIdx.x] = 0u;
    if (threadIdx.x == 0) { g_cnt_all = 0u; g_gen_all = 0u; }
}

// -------- xproj (R7-exact, known good; one-time ~250us) --------
__device__ __forceinline__ void load_tile_f32(float2 (*S)[128], const float* __restrict__ src,
                                              size_t rowbase, int ld, int k0, int tid) {
#pragma unroll
    for (int r = 0; r < 4; r++) {
        int f = r * 256 + tid;
        int row = f >> 3, fq = f & 7;
        const float4 v = *reinterpret_cast<const float4*>(
            src + (rowbase + (size_t)row) * (size_t)ld + k0 + fq * 4);
        S[2 * fq + 0][row] = make_float2(v.x, v.y);
        S[2 * fq + 1][row] = make_float2(v.z, v.w);
    }
}

__device__ __forceinline__ void compute_chunk32(const float2 (*Ss)[128], const float2 (*Ws)[128],
                                                int ty, int tx, unsigned long long (*acc)[8]) {
#pragma unroll
    for (int kp = 0; kp < KPAIRS; kp++) {
        unsigned long long s[8], w[8];
        const ulonglong2* sp = reinterpret_cast<const ulonglong2*>(&Ss[kp][ty * 8]);
#pragma unroll
        for (int q = 0; q < 4; q++) {
            ulonglong2 v = sp[q];
            s[2 * q + 0] = v.x; s[2 * q + 1] = v.y;
        }
#pragma unroll
        for (int j = 0; j < 8; j++)
            w[j] = *reinterpret_cast<const unsigned long long*>(&Ws[kp][tx + 16 * j]);
#pragma unroll
        for (int i = 0; i < 8; i++)
#pragma unroll
            for (int j = 0; j < 8; j++)
                acc[i][j] = ffma2(s[i], w[j], acc[i][j]);
    }
}

__global__ __launch_bounds__(256, 1) void xproj_kernel(const float* __restrict__ x,
                                                       const float* __restrict__ W_ih,
                                                       const float* __restrict__ b_ih,
                                                       const float* __restrict__ b_hh) {
    __shared__ alignas(16) float2 Ss[KPAIRS][128];
    __shared__ alignas(16) float2 Ws[KPAIRS][128];
    const int tid = threadIdx.x;
    const int tx = tid & 15, ty = tid >> 4;
    const int mtile = blockIdx.x, htile = blockIdx.y;

    unsigned long long acc[8][8];
#pragma unroll
    for (int i = 0; i < 8; i++)
#pragma unroll
        for (int j = 0; j < 8; j++) acc[i][j] = 0ull;

    for (int c = 0; c < N_INP / KC; c++) {
        const int k0 = c * KC;
        load_tile_f32(Ss, x,    (size_t)mtile * 128, N_INP, k0, tid);
        load_tile_f32(Ws, W_ih, (size_t)htile * 128, N_INP, k0, tid);
        __syncthreads();
        compute_chunk32(Ss, Ws, ty, tx, acc);
        __syncthreads();
    }

    const int b0 = ty * 8;
    const int hbase = htile * 128 + tx;
    float bias[8];
#pragma unroll
    for (int j = 0; j < 8; j++) {
        const int h = hbase + 16 * j;
        bias[j] = b_ih[h] + b_hh[h];
    }
#pragma unroll
    for (int i = 0; i < 8; i++) {
        const size_t row = ((size_t)mtile * 128 + b0 + i) * N_HID;
#pragma unroll
        for (int j = 0; j < 8; j++)
            g_xp[row + hbase + 16 * j] = lo32(acc[i][j]) + hi32(acc[i][j]) + bias[j];
    }
}

// -------- persistent recurrence, fine-grained sync --------
#define SM_TOTAL ((SP_F2 + WP_F2) * 8)

__global__ __launch_bounds__(TPC, 1) void rnn_persistent(const float* __restrict__ W_hh,
                                                         const float* __restrict__ W_ro,
                                                         const float* __restrict__ b_ro,
                                                         float* __restrict__ out) {
    extern __shared__ char smem[];
    float2* Sp = reinterpret_cast<float2*>(smem);
    float2* Wp = reinterpret_cast<float2*>(smem) + SP_F2;

    const int tid = threadIdx.x;
    const int tx = tid & 7, ty = tid >> 3;
    const int h = blockIdx.x >> 3;       // htile 0..15 (64-wide h tiles)
    const int j = blockIdx.x & 7;        // k-slice 0..7 (128-wide)
    const int hbase = h * 64 + 2 * tx;
    // phase-B mapping: this CTA reduces batches [16j,16j+16), cols [64h,64h+64)
    const int b_loc = tid >> 4;          // 0..15
    const int c4    = tid & 15;          // 0..15 (f4 within 64 cols)
    const int bb    = j * 16 + b_loc;    // batch row
    const int f4col = h * 16 + c4;       // f4 col within N_HID (256 f4)

    // Persist this CTA's W_hh tile (h = h*64.., k = j*128..) for all steps.
    load_tile128<64>(Wp, W_hh, (size_t)h * 64, N_HID, j * KSLICE, tid);
    // Prologue: state(t=0) = 0 -> zero Sp directly.
    for (int i = tid; i < SP_F2; i += TPC) Sp[i] = make_float2(0.f, 0.f);
    __syncthreads();

    for (int t = 0; t < T_STEPS; t++) {
        const int par = t & 1;
        // ---- phase A: partial[par][j][b][h-range] = state-slice-j @ W_hh^T ----
        unsigned long long acc[4][8];
#pragma unroll
        for (int i = 0; i < 4; i++)
#pragma unroll
            for (int q = 0; q < 8; q++) acc[i][q] = 0ull;

        compute128(Sp, Wp, ty, tx, acc);
        store_acc(g_part2[par] + (size_t)j * BATCH * N_HID, N_HID, hbase, ty, acc);

        // Prefetch xp for phase B (independent of sync).
        const float4 xpv = reinterpret_cast<const float4*>(g_xp)
            [((size_t)t * BATCH + bb) * (N_HID / 4) + f4col];

        // ---- sync 1: wait for the 8 CTAs producing partials for my h-columns ----
        __syncthreads();
        if (tid == 0) {
            __threadfence();
            atomicAdd(&g_pdone[h], 1u);
            poll_ge(&g_pdone[h], 8u * (unsigned)(t + 1));
        }
        __syncthreads();

        // ---- phase B: state[par^1][bb][64h..64h+64) = tanh(xp + sum partials) ----
        {
            float4 s = xpv;
            const float4* pb = reinterpret_cast<const float4*>(g_part2[par]);
#pragma unroll
            for (int k2 = 0; k2 < SPLITK; k2++) {
                const float4 p = pb[((size_t)k2 * BATCH + bb) * (N_HID / 4) + f4col];
                s.x += p.x; s.y += p.y; s.z += p.z; s.w += p.w;
            }
            reinterpret_cast<float4*>(g_state2[par ^ 1])
                [(size_t)bb * (N_HID / 4) + f4col] =
                make_float4(fast_tanh(s.x), fast_tanh(s.y),
                            fast_tanh(s.z), fast_tanh(s.w));
        }

        // ---- sync 2: slice j ready when its 16 producers (htiles 2j,2j+1) done ----
        __syncthreads();
        if (tid == 0) {
            __threadfence();
            atomicAdd(&g_sdone[h >> 1], 1u);
            poll_ge(&g_sdone[j], 16u * (unsigned)(t + 1));
        }
        __syncthreads();

        // ---- load next state slice j into smem ----
        load_tile128<128>(Sp, g_state2[par ^ 1], 0, N_HID, j * KSLICE, tid);
        __syncthreads();
    }

    // ---- final joint barrier, then readout (state parity 0 after 512 steps) ----
    gbar(&g_cnt_all, &g_gen_all, NCTA, 1);

    if (blockIdx.x < 16) {
        const int h2 = blockIdx.x >> 3;      // output half (64 wide)
        const int ks2 = blockIdx.x & 7;      // k-slice
        load_tile128<64>(Wp, W_ro, (size_t)h2 * 64, N_HID, ks2 * KSLICE, tid);
        load_tile128<128>(Sp, g_state2[0], 0, N_HID, ks2 * KSLICE, tid);
        __syncthreads();

        unsigned long long acc[4][8];
#pragma unroll
        for (int i = 0; i < 4; i++)
#pragma unroll
            for (int q = 0; q < 8; q++) acc[i][q] = 0ull;

        compute128(Sp, Wp, ty, tx, acc);
        store_acc(g_part2[0] + (size_t)ks2 * BATCH * N_OUT, N_OUT,
                  h2 * 64 + 2 * tx, ty, acc);
    }
    gbar(&g_cnt_all, &g_gen_all, NCTA, 2);

    if (blockIdx.x < 16) {
        const int idx = blockIdx.x * TPC + tid;   // f4 over 128x128 output
        float4 s = make_float4(0.f, 0.f, 0.f, 0.f);
#pragma unroll
        for (int k2 = 0; k2 < SPLITK; k2++) {
            const float4 p = reinterpret_cast<const float4*>(
                g_part2[0] + (size_t)k2 * BATCH * N_OUT)[idx];
            s.x += p.x; s.y += p.y; s.z += p.z; s.w += p.w;
        }
        const int o0 = (idx * 4) & (N_OUT - 1);
        const float4 bb2 = *reinterpret_cast<const float4*>(b_ro + o0);
        s.x += bb2.x; s.y += bb2.y; s.z += bb2.z; s.w += bb2.w;
        reinterpret_cast<float4*>(out)[idx] = s;
    }
}

// -------- launch (3 graph nodes) --------
extern "C" void kernel_launch(void* const* d_in, const int* in_sizes, int n_in,
                              void* d_out, int out_size) {
    const float* x    = (const float*)d_in[0];   // [512,128,256]
    const float* W_ih = (const float*)d_in[1];   // [1024,256]
    const float* W_hh = (const float*)d_in[2];   // [1024,1024]
    const float* b_ih = (const float*)d_in[3];   // [1024]
    const float* b_hh = (const float*)d_in[4];   // [1024]
    const float* W_ro = (const float*)d_in[5];   // [128,1024]
    const float* b_ro = (const float*)d_in[6];   // [128]
    float* out = (float*)d_out;                  // [128,128]

    (void)in_sizes; (void)n_in; (void)out_size;

    // Idempotent, capture-safe.
    cudaFuncSetAttribute(rnn_persistent,
                         cudaFuncAttributeMaxDynamicSharedMemorySize, SM_TOTAL);

    init_kernel<<<1, 32>>>();
    xproj_kernel<<<dim3(T_STEPS * BATCH / 128, N_HID / 128), 256>>>(x, W_ih, b_ih, b_hh);
    rnn_persistent<<<NCTA, TPC, SM_TOTAL>>>(W_hh, W_ro, b_ro, out);
}